// round 6
// baseline (speedup 1.0000x reference)
#include <cuda_runtime.h>
#include <math.h>

// Problem shapes (fixed by the dataset's setup_inputs)
#define BATCH   2
#define NMAPS   16
#define CH      256
#define HWPIX   4096   // 64*64
#define TDIM    1024
#define PIX     64     // pixels per block tile
#define NPQ     (PIX/4)                 // 16 pixel-quads
#define NTHREADS 512
#define NSTAGE  3
#define SMEM_BYTES (NSTAGE * CH * PIX * 4)   // 3 x 64KB slab buffers

// Intermediates in device globals (no allocation allowed)
__device__ float  g_qk[BATCH * CH];    // qk = scale * Wk^T (Wq tr + bq)
__device__ float4 g_wvp[128 * 128];    // paired Wv: [P][c2] = {w(2P,2c2),w(2P+1,2c2),w(2P,2c2+1),w(2P+1,2c2+1)}

// ---------------- f32x2 packed-FP32 helpers ----------------
__device__ __forceinline__ unsigned long long pk2(float lo, float hi) {
    unsigned long long r;
    asm("mov.b64 %0, {%1, %2};" : "=l"(r) : "f"(lo), "f"(hi));
    return r;
}
__device__ __forceinline__ unsigned long long splat2(float v) {
    unsigned long long r;
    asm("mov.b64 %0, {%1, %1};" : "=l"(r) : "f"(v));
    return r;
}
__device__ __forceinline__ void fma2(unsigned long long& d, unsigned long long a, unsigned long long b) {
    asm("fma.rn.f32x2 %0, %1, %2, %0;" : "+l"(d) : "l"(a), "l"(b));
}
__device__ __forceinline__ void upk2(float& lo, float& hi, unsigned long long v) {
    asm("mov.b64 {%0, %1}, %2;" : "=f"(lo), "=f"(hi) : "l"(v));
}

// ---------------- cp.async helpers ----------------
__device__ __forceinline__ void cp16(float* dst_smem, const float* src) {
    unsigned d = (unsigned)__cvta_generic_to_shared(dst_smem);
    asm volatile("cp.async.cg.shared.global [%0], [%1], 16;" :: "r"(d), "l"(src));
}
__device__ __forceinline__ void cp_commit() { asm volatile("cp.async.commit_group;" ::: "memory"); }
__device__ __forceinline__ void cp_wait0()  { asm volatile("cp.async.wait_group 0;" ::: "memory"); }
__device__ __forceinline__ void cp_wait2()  { asm volatile("cp.async.wait_group 2;" ::: "memory"); }

// ---------------- Fused prep kernel ----------------
// Blocks 0..15  : (b = blk>>3, 32-column chunk of qk). Each block recomputes
//                 q[b][:] redundantly (Wq shared via L2), then its qk columns.
// Blocks 16..79 : pair Wv into g_wvp for the f32x2 epilogue.
__global__ void __launch_bounds__(256) prep_kernel(
    const float* __restrict__ tr, const float* __restrict__ Wq,
    const float* __restrict__ bq, const float* __restrict__ Wk,
    const float* __restrict__ Wv)
{
    const int blk = blockIdx.x;
    const int tid = threadIdx.x;

    if (blk >= 16) {
        // --- Wv pairing: idx over 16384 float4 outputs ---
        const int idx = (blk - 16) * 256 + tid;   // 0..16383
        const int P   = idx >> 7;
        const int c2  = idx & 127;
        const float2 r0 = *(const float2*)(Wv + (size_t)(2 * P)     * CH + 2 * c2);
        const float2 r1 = *(const float2*)(Wv + (size_t)(2 * P + 1) * CH + 2 * c2);
        g_wvp[idx] = make_float4(r0.x, r1.x, r0.y, r1.y);
        return;
    }

    // --- qk chunk ---
    __shared__ float q_s[CH];
    __shared__ float part[8][32];
    const int b    = blk >> 3;          // 0..1
    const int c0   = (blk & 7) * 32;    // column chunk
    const int lane = tid & 31;
    const int wid  = tid >> 5;          // 8 warps

    // q[o] = tr[b,:]·Wq[o,:] + bq[o]; warp handles o = wid + 8*r
    const float4* t4 = (const float4*)(tr + (size_t)b * TDIM);
    #pragma unroll 1
    for (int r = 0; r < 32; r++) {
        const int o = wid + 8 * r;
        const float4* w4 = (const float4*)(Wq + (size_t)o * TDIM);
        float a0 = 0.f, a1 = 0.f, a2 = 0.f, a3 = 0.f;
        #pragma unroll
        for (int k = 0; k < 8; k++) {
            float4 w = w4[lane + 32 * k];
            float4 t = t4[lane + 32 * k];
            a0 += w.x * t.x; a1 += w.y * t.y; a2 += w.z * t.z; a3 += w.w * t.w;
        }
        float acc = (a0 + a1) + (a2 + a3);
        #pragma unroll
        for (int off = 16; off > 0; off >>= 1) acc += __shfl_xor_sync(0xffffffffu, acc, off);
        if (lane == 0) q_s[o] = acc + bq[o];
    }
    __syncthreads();

    // qk[c] = scale * sum_o q[o] * Wk[o][c] over this block's 32 columns
    const int og = tid >> 5;   // 0..7 (o-group)
    const int ci = tid & 31;
    const int c  = c0 + ci;
    float acc = 0.f;
    #pragma unroll 8
    for (int i = 0; i < 32; i++) {
        int o = og * 32 + i;
        acc += q_s[o] * Wk[(size_t)o * CH + c];
    }
    part[og][ci] = acc;
    __syncthreads();
    if (tid < 32) {
        float s = part[0][ci] + part[1][ci] + part[2][ci] + part[3][ci]
                + part[4][ci] + part[5][ci] + part[6][ci] + part[7][ci];
        g_qk[b * CH + c0 + ci] = s * 0.0625f;   // CH^-0.5
    }
}

// ---------------- Main: fused scores + online softmax + weighted sum + f32x2 GEMM ----------------
__global__ void __launch_bounds__(NTHREADS, 1) main_kernel(
    const float* __restrict__ xg, const float* __restrict__ bv,
    float* __restrict__ out)
{
    extern __shared__ float smem[];          // NSTAGE buffers of CH*PIX floats
    __shared__ float qk_s[CH];
    __shared__ float red_s[PIX][33];         // [pixel][cg], padded pitch
    __shared__ __align__(16) float w_s[PIX];
    __shared__ __align__(16) float corr_s[PIX];
    __shared__ float rmax_s[PIX];
    __shared__ float rsum_s[PIX];

    const int tid  = threadIdx.x;
    const int b    = blockIdx.x / (HWPIX / PIX);
    const int pix0 = (blockIdx.x % (HWPIX / PIX)) * PIX;

    float* buf[NSTAGE] = { smem, smem + CH * PIX, smem + 2 * CH * PIX };

    for (int i = tid; i < CH; i += NTHREADS) qk_s[i] = g_qk[b * CH + i];
    if (tid < PIX) { rmax_s[tid] = -1e30f; rsum_s[tid] = 0.f; }

    // Thread owns channels cg*8..cg*8+7 and pixel quad pq (pixels 4pq..4pq+3)
    const int cg = tid >> 4;   // 0..31
    const int pq = tid & 15;   // 0..15

    const float* base = xg + (size_t)b * NMAPS * CH * HWPIX + pix0;

    // prologue: stage slabs 0 and 1
    #pragma unroll
    for (int s = 0; s < 2; s++) {
        const float* bm = base + (size_t)s * CH * HWPIX;
        #pragma unroll
        for (int k = 0; k < 8; k++) {
            int i4 = tid + k * NTHREADS;     // 0..4095
            int c  = i4 >> 4;
            int q  = i4 & 15;
            cp16(buf[s] + i4 * 4, bm + (size_t)c * HWPIX + 4 * q);
        }
        cp_commit();
    }
    __syncthreads();   // qk_s / softmax state visible

    float qkr[8];
    #pragma unroll
    for (int i = 0; i < 8; i++) qkr[i] = qk_s[cg * 8 + i];

    float4 yacc[8];
    #pragma unroll
    for (int i = 0; i < 8; i++) yacc[i] = make_float4(0.f, 0.f, 0.f, 0.f);

    for (int m = 0; m < NMAPS; m++) {
        float* bufc = buf[m % NSTAGE];
        if (m + 2 < NMAPS) {
            float* bufn = buf[(m + 2) % NSTAGE];
            const float* bm = base + (size_t)(m + 2) * CH * HWPIX;
            #pragma unroll
            for (int k = 0; k < 8; k++) {
                int i4 = tid + k * NTHREADS;
                int c  = i4 >> 4;
                int q  = i4 & 15;
                cp16(bufn + i4 * 4, bm + (size_t)c * HWPIX + 4 * q);
            }
            cp_commit();
            cp_wait2();   // <=2 groups pending -> slab m complete
        } else {
            cp_wait0();
        }
        __syncthreads();   // sync A: slab m ready; red_s free

        // Phase A: x -> registers; partial scores for this thread's 4 pixels
        float4 xv[8];
        float4 ps = make_float4(0.f, 0.f, 0.f, 0.f);
        {
            const float4* x4 = (const float4*)bufc;
            #pragma unroll
            for (int i = 0; i < 8; i++) {
                int c = cg * 8 + i;
                xv[i] = x4[c * NPQ + pq];
                ps.x += qkr[i] * xv[i].x;
                ps.y += qkr[i] * xv[i].y;
                ps.z += qkr[i] * xv[i].z;
                ps.w += qkr[i] * xv[i].w;
            }
            red_s[4 * pq + 0][cg] = ps.x;
            red_s[4 * pq + 1][cg] = ps.y;
            red_s[4 * pq + 2][cg] = ps.z;
            red_s[4 * pq + 3][cg] = ps.w;
        }
        __syncthreads();   // sync B: bufc reads + red_s writes done

        // Reduce 32 cg-partials per pixel + online softmax (64 threads)
        if (tid < PIX) {
            float s0 = 0.f, s1 = 0.f, s2 = 0.f, s3 = 0.f;
            #pragma unroll
            for (int g = 0; g < 32; g += 4) {
                s0 += red_s[tid][g];
                s1 += red_s[tid][g + 1];
                s2 += red_s[tid][g + 2];
                s3 += red_s[tid][g + 3];
            }
            float s  = (s0 + s1) + (s2 + s3);
            float om = rmax_s[tid];
            float nm = fmaxf(om, s);
            float cr = __expf(om - nm);
            float w  = __expf(s - nm);
            rsum_s[tid] = rsum_s[tid] * cr + w;
            rmax_s[tid] = nm;
            w_s[tid]    = w;
            corr_s[tid] = cr;
        }
        __syncthreads();   // sync C: w/corr ready

        // Phase B: y = y*corr + w*x  (pure register work)
        {
            float4 wv = *(const float4*)&w_s[4 * pq];
            float4 cv = *(const float4*)&corr_s[4 * pq];
            #pragma unroll
            for (int i = 0; i < 8; i++) {
                yacc[i].x = yacc[i].x * cv.x + wv.x * xv[i].x;
                yacc[i].y = yacc[i].y * cv.y + wv.y * xv[i].y;
                yacc[i].z = yacc[i].z * cv.z + wv.z * xv[i].z;
                yacc[i].w = yacc[i].w * cv.w + wv.w * xv[i].w;
            }
        }
        // no sync: cp.async issue for this buffer slot happens 2 iterations
        // later, always after this iteration's sync B/C.
    }

    // normalize y into buf0 (free: last slabs live in other stages)
    __syncthreads();
    {
        float4 rs = *(const float4*)&rsum_s[4 * pq];
        float4 inv = make_float4(1.f / rs.x, 1.f / rs.y, 1.f / rs.z, 1.f / rs.w);
        float4* y4 = (float4*)buf[0];
        #pragma unroll
        for (int i = 0; i < 8; i++) {
            int c = cg * 8 + i;
            y4[c * NPQ + pq] = make_float4(yacc[i].x * inv.x, yacc[i].y * inv.y,
                                           yacc[i].z * inv.z, yacc[i].w * inv.w);
        }
    }
    __syncthreads();

    // Epilogue GEMM via packed f32x2: out[o,p] = sum_c Wv[o,c]*y[c,p] + bv[o]
    // Thread owns o-pairs P = og*4+k (o = og*8..og*8+7) x 4 pixels (4pq..+3)
    {
        const int og = tid >> 4;   // 0..31
        unsigned long long acc2[4][4];   // [pair k][pixel j] packed (o_even, o_odd)
        #pragma unroll
        for (int k = 0; k < 4; k++) {
            unsigned long long bp = pk2(bv[og * 8 + 2 * k], bv[og * 8 + 2 * k + 1]);
            #pragma unroll
            for (int j = 0; j < 4; j++) acc2[k][j] = bp;
        }
        const float4* y4 = (const float4*)buf[0];

        #pragma unroll 2
        for (int c2 = 0; c2 < 128; c2++) {       // c = 2*c2, 2*c2+1
            float4 y0 = y4[(2 * c2 + 0) * NPQ + pq];
            float4 y1 = y4[(2 * c2 + 1) * NPQ + pq];
            unsigned long long ys0[4], ys1[4];
            ys0[0] = splat2(y0.x); ys0[1] = splat2(y0.y); ys0[2] = splat2(y0.z); ys0[3] = splat2(y0.w);
            ys1[0] = splat2(y1.x); ys1[1] = splat2(y1.y); ys1[2] = splat2(y1.z); ys1[3] = splat2(y1.w);
            #pragma unroll
            for (int k = 0; k < 4; k++) {
                float4 wp = g_wvp[(size_t)(og * 4 + k) * 128 + c2];
                unsigned long long wc0 = pk2(wp.x, wp.y);
                unsigned long long wc1 = pk2(wp.z, wp.w);
                #pragma unroll
                for (int j = 0; j < 4; j++) {
                    fma2(acc2[k][j], wc0, ys0[j]);
                    fma2(acc2[k][j], wc1, ys1[j]);
                }
            }
        }

        // unpack + vectorized stores: one float4 (4 pixels) per output channel
        #pragma unroll
        for (int k = 0; k < 4; k++) {
            float lo[4], hi[4];
            #pragma unroll
            for (int j = 0; j < 4; j++) upk2(lo[j], hi[j], acc2[k][j]);
            int o0 = og * 8 + 2 * k;
            float* dst0 = out + ((size_t)b * CH + o0)     * HWPIX + pix0 + 4 * pq;
            float* dst1 = out + ((size_t)b * CH + o0 + 1) * HWPIX + pix0 + 4 * pq;
            *(float4*)dst0 = make_float4(lo[0], lo[1], lo[2], lo[3]);
            *(float4*)dst1 = make_float4(hi[0], hi[1], hi[2], hi[3]);
        }
    }
}

extern "C" void kernel_launch(void* const* d_in, const int* in_sizes, int n_in,
                              void* d_out, int out_size)
{
    const float* tr = (const float*)d_in[0];   // [B, T]
    const float* x  = (const float*)d_in[1];   // [B, M, C, H, W]
    const float* Wq = (const float*)d_in[2];   // [C, T]
    const float* bq = (const float*)d_in[3];   // [C]
    const float* Wk = (const float*)d_in[4];   // [C, C]
    // d_in[5] = bk: constant across the softmax axis -> cancels, unused
    const float* Wv = (const float*)d_in[6];   // [C, C]
    const float* bv = (const float*)d_in[7];   // [C]
    float* out = (float*)d_out;                // [B, C, H, W]

    (void)in_sizes; (void)n_in; (void)out_size;

    cudaFuncSetAttribute(main_kernel, cudaFuncAttributeMaxDynamicSharedMemorySize, SMEM_BYTES);

    prep_kernel<<<80, 256>>>(tr, Wq, bq, Wk, Wv);
    main_kernel<<<BATCH * (HWPIX / PIX), NTHREADS, SMEM_BYTES>>>(x, bv, out);
}

// round 7
// speedup vs baseline: 1.5573x; 1.5573x over previous
#include <cuda_runtime.h>
#include <math.h>

// Problem shapes (fixed by the dataset's setup_inputs)
#define BATCH   2
#define NMAPS   16
#define CH      256
#define HWPIX   4096   // 64*64
#define TDIM    1024
#define PIX     64     // pixels per block tile
#define NPQ     (PIX/4)                 // 16 pixel-quads
#define NTHREADS 512
#define YSMEM_BYTES (CH * PIX * 4)      // 64KB dynamic smem for y

// Intermediates in device globals (no allocation allowed)
__device__ float  g_q[BATCH * CH];     // q = tr @ Wq^T + bq
__device__ float  g_qk[BATCH * CH];    // qk = scale * Wk^T q
__device__ float4 g_wvp[128 * 128];    // paired Wv: [P][c2] = {w(2P,2c2),w(2P+1,2c2),w(2P,2c2+1),w(2P+1,2c2+1)}

// ---------------- f32x2 packed-FP32 helpers ----------------
__device__ __forceinline__ unsigned long long pk2(float lo, float hi) {
    unsigned long long r;
    asm("mov.b64 %0, {%1, %2};" : "=l"(r) : "f"(lo), "f"(hi));
    return r;
}
__device__ __forceinline__ unsigned long long splat2(float v) {
    unsigned long long r;
    asm("mov.b64 %0, {%1, %1};" : "=l"(r) : "f"(v));
    return r;
}
__device__ __forceinline__ void fma2(unsigned long long& d, unsigned long long a, unsigned long long b) {
    asm("fma.rn.f32x2 %0, %1, %2, %0;" : "+l"(d) : "l"(a), "l"(b));
}
__device__ __forceinline__ void upk2(float& lo, float& hi, unsigned long long v) {
    asm("mov.b64 {%0, %1}, %2;" : "=f"(lo), "=f"(hi) : "l"(v));
}

// ---------------- Prep A: q rows (blocks 0..63) + Wv pairing (blocks 64..127) ----------------
__global__ void __launch_bounds__(256) prepA_kernel(
    const float* __restrict__ tr, const float* __restrict__ Wq,
    const float* __restrict__ bq, const float* __restrict__ Wv)
{
    const int blk = blockIdx.x;
    const int tid = threadIdx.x;

    if (blk >= 64) {
        // Wv pairing: 16384 float4 outputs
        const int idx = (blk - 64) * 256 + tid;
        const int P   = idx >> 7;
        const int c2  = idx & 127;
        const float2 r0 = *(const float2*)(Wv + (size_t)(2 * P)     * CH + 2 * c2);
        const float2 r1 = *(const float2*)(Wv + (size_t)(2 * P + 1) * CH + 2 * c2);
        g_wvp[idx] = make_float4(r0.x, r1.x, r0.y, r1.y);
        return;
    }

    // q[b][o] = tr[b,:]·Wq[o,:] + bq[o]; warp per o
    const int b    = blk >> 5;           // 0..1
    const int lane = tid & 31;
    const int wid  = tid >> 5;           // 8 warps
    const int o    = (blk & 31) * 8 + wid;

    const float4* w4 = (const float4*)(Wq + (size_t)o * TDIM);
    const float4* t4 = (const float4*)(tr + (size_t)b * TDIM);
    float a0 = 0.f, a1 = 0.f, a2 = 0.f, a3 = 0.f;
    #pragma unroll
    for (int k = 0; k < 8; k++) {
        float4 w = w4[lane + 32 * k];
        float4 t = t4[lane + 32 * k];
        a0 += w.x * t.x; a1 += w.y * t.y; a2 += w.z * t.z; a3 += w.w * t.w;
    }
    float acc = (a0 + a1) + (a2 + a3);
    #pragma unroll
    for (int off = 16; off > 0; off >>= 1) acc += __shfl_xor_sync(0xffffffffu, acc, off);
    if (lane == 0) g_q[b * CH + o] = acc + bq[o];
}

// ---------------- Prep B: qk[b][c] = scale * sum_o q[b,o]*Wk[o,c] ----------------
__global__ void __launch_bounds__(256) prepB_kernel(const float* __restrict__ Wk)
{
    __shared__ float part[8][32];
    const int b  = blockIdx.y;
    const int c0 = blockIdx.x * 32;
    const int og = threadIdx.x >> 5;
    const int ci = threadIdx.x & 31;
    const int c  = c0 + ci;

    const float* qb = g_q + b * CH;
    float acc = 0.f;
    #pragma unroll 8
    for (int i = 0; i < 32; i++) {
        int o = og * 32 + i;
        acc += qb[o] * Wk[(size_t)o * CH + c];
    }
    part[og][ci] = acc;
    __syncthreads();
    if (threadIdx.x < 32) {
        float s = part[0][ci] + part[1][ci] + part[2][ci] + part[3][ci]
                + part[4][ci] + part[5][ci] + part[6][ci] + part[7][ci];
        g_qk[b * CH + c0 + ci] = s * 0.0625f;   // CH^-0.5
    }
}

// ---------------- Main: direct-LDG pipelined scores + online softmax + f32x2 GEMM ----------------
__global__ void __launch_bounds__(NTHREADS) main_kernel(
    const float* __restrict__ xg, const float* __restrict__ bv,
    float* __restrict__ out)
{
    extern __shared__ float ysh[];           // CH*PIX floats (y buffer)
    __shared__ float red_s[PIX][33];         // [pixel][cg], padded pitch
    __shared__ __align__(16) float w_s[PIX];
    __shared__ __align__(16) float corr_s[PIX];
    __shared__ float rmax_s[PIX];
    __shared__ float rsum_s[PIX];

    const int tid  = threadIdx.x;
    const int b    = blockIdx.x / (HWPIX / PIX);
    const int pix0 = (blockIdx.x % (HWPIX / PIX)) * PIX;

    // Thread owns channels cg*8..cg*8+7 and pixel quad pq (pixels 4pq..4pq+3)
    const int cg = tid >> 4;   // 0..31
    const int pq = tid & 15;   // 0..15

    if (tid < PIX) { rmax_s[tid] = -1e30f; rsum_s[tid] = 0.f; }

    // qk straight from gmem (L2-resident after prepB)
    float qkr[8];
    #pragma unroll
    for (int i = 0; i < 8; i++) qkr[i] = g_qk[b * CH + cg * 8 + i];

    // per-thread gmem base: x[b][m][cg*8 + i][pix0 + 4pq .. +3]
    const float* xb = xg + ((size_t)b * NMAPS * CH + cg * 8) * HWPIX + pix0 + 4 * pq;

    // register double-buffer: cur = slab m, nxt = slab m+1
    float4 cur[8], nxt[8];
    #pragma unroll
    for (int i = 0; i < 8; i++) cur[i] = *(const float4*)(xb + (size_t)i * HWPIX);

    float4 yacc[8];
    #pragma unroll
    for (int i = 0; i < 8; i++) yacc[i] = make_float4(0.f, 0.f, 0.f, 0.f);

    #pragma unroll
    for (int m = 0; m < NMAPS; m++) {
        // prefetch next slab into registers (independent LDG.128s, front-batched)
        if (m + 1 < NMAPS) {
            const float* p = xb + (size_t)(m + 1) * CH * HWPIX;
            #pragma unroll
            for (int i = 0; i < 8; i++) nxt[i] = *(const float4*)(p + (size_t)i * HWPIX);
        }

        // partial scores for this thread's 4 pixels over its 8 channels
        float4 ps = make_float4(0.f, 0.f, 0.f, 0.f);
        #pragma unroll
        for (int i = 0; i < 8; i++) {
            ps.x += qkr[i] * cur[i].x;
            ps.y += qkr[i] * cur[i].y;
            ps.z += qkr[i] * cur[i].z;
            ps.w += qkr[i] * cur[i].w;
        }
        red_s[4 * pq + 0][cg] = ps.x;
        red_s[4 * pq + 1][cg] = ps.y;
        red_s[4 * pq + 2][cg] = ps.z;
        red_s[4 * pq + 3][cg] = ps.w;
        __syncthreads();   // sync B: partials visible

        // reduce 32 cg-partials per pixel + online softmax (64 threads)
        if (tid < PIX) {
            float s0 = 0.f, s1 = 0.f, s2 = 0.f, s3 = 0.f;
            #pragma unroll
            for (int g = 0; g < 32; g += 4) {
                s0 += red_s[tid][g];
                s1 += red_s[tid][g + 1];
                s2 += red_s[tid][g + 2];
                s3 += red_s[tid][g + 3];
            }
            float s  = (s0 + s1) + (s2 + s3);
            float om = rmax_s[tid];
            float nm = fmaxf(om, s);
            float cr = __expf(om - nm);
            float w  = __expf(s - nm);
            rsum_s[tid] = rsum_s[tid] * cr + w;
            rmax_s[tid] = nm;
            w_s[tid]    = w;
            corr_s[tid] = cr;
        }
        __syncthreads();   // sync C: w/corr ready (also gates red_s reuse next iter)

        // y = y*corr + w*x (registers only)
        {
            float4 wv = *(const float4*)&w_s[4 * pq];
            float4 cv = *(const float4*)&corr_s[4 * pq];
            #pragma unroll
            for (int i = 0; i < 8; i++) {
                yacc[i].x = yacc[i].x * cv.x + wv.x * cur[i].x;
                yacc[i].y = yacc[i].y * cv.y + wv.y * cur[i].y;
                yacc[i].z = yacc[i].z * cv.z + wv.z * cur[i].z;
                yacc[i].w = yacc[i].w * cv.w + wv.w * cur[i].w;
            }
        }
        #pragma unroll
        for (int i = 0; i < 8; i++) cur[i] = nxt[i];
    }

    // normalize y and write to smem in [c][pq] layout (conflict-free STS.128)
    {
        float4 rs = *(const float4*)&rsum_s[4 * pq];
        float4 inv = make_float4(1.f / rs.x, 1.f / rs.y, 1.f / rs.z, 1.f / rs.w);
        float4* y4 = (float4*)ysh;
        #pragma unroll
        for (int i = 0; i < 8; i++) {
            int c = cg * 8 + i;
            y4[c * NPQ + pq] = make_float4(yacc[i].x * inv.x, yacc[i].y * inv.y,
                                           yacc[i].z * inv.z, yacc[i].w * inv.w);
        }
    }
    __syncthreads();

    // Epilogue GEMM via packed f32x2: out[o,p] = sum_c Wv[o,c]*y[c,p] + bv[o]
    // Thread owns o-pairs P = og*4+k (o = og*8..og*8+7) x 4 pixels (4pq..+3)
    {
        const int og = tid >> 4;   // 0..31
        unsigned long long acc2[4][4];   // [pair k][pixel j] packed (o_even, o_odd)
        #pragma unroll
        for (int k = 0; k < 4; k++) {
            unsigned long long bp = pk2(bv[og * 8 + 2 * k], bv[og * 8 + 2 * k + 1]);
            #pragma unroll
            for (int j = 0; j < 4; j++) acc2[k][j] = bp;
        }
        const float4* y4 = (const float4*)ysh;
        const ulonglong2* wv2 = (const ulonglong2*)g_wvp;   // .x=(w even,w odd)@c, .y=@c+1

        #pragma unroll 8
        for (int c2 = 0; c2 < 128; c2++) {       // channels 2*c2, 2*c2+1
            float4 y0 = y4[(2 * c2 + 0) * NPQ + pq];
            float4 y1 = y4[(2 * c2 + 1) * NPQ + pq];
            unsigned long long ys0[4], ys1[4];
            ys0[0] = splat2(y0.x); ys0[1] = splat2(y0.y); ys0[2] = splat2(y0.z); ys0[3] = splat2(y0.w);
            ys1[0] = splat2(y1.x); ys1[1] = splat2(y1.y); ys1[2] = splat2(y1.z); ys1[3] = splat2(y1.w);
            #pragma unroll
            for (int k = 0; k < 4; k++) {
                ulonglong2 wp = wv2[(size_t)(og * 4 + k) * 128 + c2];
                #pragma unroll
                for (int j = 0; j < 4; j++) {
                    fma2(acc2[k][j], wp.x, ys0[j]);
                    fma2(acc2[k][j], wp.y, ys1[j]);
                }
            }
        }

        // unpack + vectorized stores
        #pragma unroll
        for (int k = 0; k < 4; k++) {
            float lo[4], hi[4];
            #pragma unroll
            for (int j = 0; j < 4; j++) upk2(lo[j], hi[j], acc2[k][j]);
            int o0 = og * 8 + 2 * k;
            float* dst0 = out + ((size_t)b * CH + o0)     * HWPIX + pix0 + 4 * pq;
            float* dst1 = out + ((size_t)b * CH + o0 + 1) * HWPIX + pix0 + 4 * pq;
            *(float4*)dst0 = make_float4(lo[0], lo[1], lo[2], lo[3]);
            *(float4*)dst1 = make_float4(hi[0], hi[1], hi[2], hi[3]);
        }
    }
}

extern "C" void kernel_launch(void* const* d_in, const int* in_sizes, int n_in,
                              void* d_out, int out_size)
{
    const float* tr = (const float*)d_in[0];   // [B, T]
    const float* x  = (const float*)d_in[1];   // [B, M, C, H, W]
    const float* Wq = (const float*)d_in[2];   // [C, T]
    const float* bq = (const float*)d_in[3];   // [C]
    const float* Wk = (const float*)d_in[4];   // [C, C]
    // d_in[5] = bk: constant across the softmax axis -> cancels, unused
    const float* Wv = (const float*)d_in[6];   // [C, C]
    const float* bv = (const float*)d_in[7];   // [C]
    float* out = (float*)d_out;                // [B, C, H, W]

    (void)in_sizes; (void)n_in; (void)out_size;

    cudaFuncSetAttribute(main_kernel, cudaFuncAttributeMaxDynamicSharedMemorySize, YSMEM_BYTES);

    prepA_kernel<<<128, 256>>>(tr, Wq, bq, Wv);
    prepB_kernel<<<dim3(8, BATCH), 256>>>(Wk);
    main_kernel<<<BATCH * (HWPIX / PIX), NTHREADS, YSMEM_BYTES>>>(x, bv, out);
}

// round 8
// speedup vs baseline: 1.6889x; 1.0845x over previous
#include <cuda_runtime.h>
#include <math.h>

// Problem shapes (fixed by the dataset's setup_inputs)
#define BATCH   2
#define NMAPS   16
#define CH      256
#define HWPIX   4096   // 64*64
#define TDIM    1024
#define PIX     64     // pixels per block tile
#define NPQ     (PIX/4)                 // 16 pixel-quads
#define NTHREADS 512
#define YPITCH  72                      // y smem row pitch (floats): bank = 8k+n, conflict-free
#define YSMEM_BYTES (CH * YPITCH * 4)   // 73728 B

// Intermediates in device globals (no allocation allowed)
__device__ float g_q[BATCH * CH];     // q = tr @ Wq^T + bq
__device__ float g_qk[BATCH * CH];    // qk = scale * Wk^T q
__device__ float g_wvt[CH * CH];      // Wv pre-rounded to tf32 bit patterns

// ---------------- tf32 helpers ----------------
__device__ __forceinline__ unsigned f2tf32(float f) {
    unsigned u;
    asm("cvt.rna.tf32.f32 %0, %1;" : "=r"(u) : "f"(f));
    return u;
}
__device__ __forceinline__ void mma_tf32(
    float& d0, float& d1, float& d2, float& d3,
    unsigned a0, unsigned a1, unsigned a2, unsigned a3,
    unsigned b0, unsigned b1)
{
    asm("mma.sync.aligned.m16n8k8.row.col.f32.tf32.tf32.f32 "
        "{%0,%1,%2,%3}, {%4,%5,%6,%7}, {%8,%9}, {%0,%1,%2,%3};"
        : "+f"(d0), "+f"(d1), "+f"(d2), "+f"(d3)
        : "r"(a0), "r"(a1), "r"(a2), "r"(a3), "r"(b0), "r"(b1));
}

// ---------------- Prep A: q rows (blocks 0..63) + Wv tf32 rounding (blocks 64..127) ----------------
__global__ void __launch_bounds__(256) prepA_kernel(
    const float* __restrict__ tr, const float* __restrict__ Wq,
    const float* __restrict__ bq, const float* __restrict__ Wv)
{
    const int blk = blockIdx.x;
    const int tid = threadIdx.x;

    if (blk >= 64) {
        // round Wv to tf32 bit patterns: 16384 float4s
        const int idx = (blk - 64) * 256 + tid;    // 0..16383
        float4 v = ((const float4*)Wv)[idx];
        float4 r = make_float4(__uint_as_float(f2tf32(v.x)),
                               __uint_as_float(f2tf32(v.y)),
                               __uint_as_float(f2tf32(v.z)),
                               __uint_as_float(f2tf32(v.w)));
        ((float4*)g_wvt)[idx] = r;
        return;
    }

    // q[b][o] = tr[b,:]·Wq[o,:] + bq[o]; warp per o
    const int b    = blk >> 5;           // 0..1
    const int lane = tid & 31;
    const int wid  = tid >> 5;           // 8 warps
    const int o    = (blk & 31) * 8 + wid;

    const float4* w4 = (const float4*)(Wq + (size_t)o * TDIM);
    const float4* t4 = (const float4*)(tr + (size_t)b * TDIM);
    float a0 = 0.f, a1 = 0.f, a2 = 0.f, a3 = 0.f;
    #pragma unroll
    for (int k = 0; k < 8; k++) {
        float4 w = w4[lane + 32 * k];
        float4 t = t4[lane + 32 * k];
        a0 += w.x * t.x; a1 += w.y * t.y; a2 += w.z * t.z; a3 += w.w * t.w;
    }
    float acc = (a0 + a1) + (a2 + a3);
    #pragma unroll
    for (int off = 16; off > 0; off >>= 1) acc += __shfl_xor_sync(0xffffffffu, acc, off);
    if (lane == 0) g_q[b * CH + o] = acc + bq[o];
}

// ---------------- Prep B: qk[b][c] = scale * sum_o q[b,o]*Wk[o,c] ----------------
__global__ void __launch_bounds__(256) prepB_kernel(const float* __restrict__ Wk)
{
    __shared__ float part[8][32];
    const int b  = blockIdx.y;
    const int c0 = blockIdx.x * 32;
    const int og = threadIdx.x >> 5;
    const int ci = threadIdx.x & 31;
    const int c  = c0 + ci;

    const float* qb = g_q + b * CH;
    float acc = 0.f;
    #pragma unroll 8
    for (int i = 0; i < 32; i++) {
        int o = og * 32 + i;
        acc += qb[o] * Wk[(size_t)o * CH + c];
    }
    part[og][ci] = acc;
    __syncthreads();
    if (threadIdx.x < 32) {
        float s = part[0][ci] + part[1][ci] + part[2][ci] + part[3][ci]
                + part[4][ci] + part[5][ci] + part[6][ci] + part[7][ci];
        g_qk[b * CH + c0 + ci] = s * 0.0625f;   // CH^-0.5
    }
}

// ---------------- Main: direct-LDG pipelined scores + online softmax + tf32 MMA epilogue ----------------
__global__ void __launch_bounds__(NTHREADS) main_kernel(
    const float* __restrict__ xg, const float* __restrict__ bv,
    float* __restrict__ out)
{
    extern __shared__ float ysh[];           // CH x YPITCH floats (y, tf32 bit patterns)
    __shared__ float red_s[PIX][33];         // [pixel][cg], padded pitch
    __shared__ __align__(16) float w_s[PIX];
    __shared__ __align__(16) float corr_s[PIX];
    __shared__ __align__(16) float rsum_s[PIX];

    const int tid  = threadIdx.x;
    const int b    = blockIdx.x / (HWPIX / PIX);
    const int pix0 = (blockIdx.x % (HWPIX / PIX)) * PIX;

    // Thread owns channels cg*8..cg*8+7 and pixel quad pq (pixels 4pq..4pq+3)
    const int cg = tid >> 4;   // 0..31
    const int pq = tid & 15;   // 0..15

    // online-softmax state in registers (valid on lanes with (tid&7)==0; pixel = tid>>3)
    float rmax_r = -1e30f, rsum_r = 0.f;

    // qk straight from gmem (L2-resident after prepB)
    float qkr[8];
    #pragma unroll
    for (int i = 0; i < 8; i++) qkr[i] = g_qk[b * CH + cg * 8 + i];

    // per-thread gmem base: x[b][m][cg*8 + i][pix0 + 4pq .. +3]
    const float* xb = xg + ((size_t)b * NMAPS * CH + cg * 8) * HWPIX + pix0 + 4 * pq;

    // register double-buffer: cur = slab m, nxt = slab m+1
    float4 cur[8], nxt[8];
    #pragma unroll
    for (int i = 0; i < 8; i++) cur[i] = *(const float4*)(xb + (size_t)i * HWPIX);

    float4 yacc[8];
    #pragma unroll
    for (int i = 0; i < 8; i++) yacc[i] = make_float4(0.f, 0.f, 0.f, 0.f);

    #pragma unroll
    for (int m = 0; m < NMAPS; m++) {
        // prefetch next slab into registers (independent LDG.128s)
        if (m + 1 < NMAPS) {
            const float* p = xb + (size_t)(m + 1) * CH * HWPIX;
            #pragma unroll
            for (int i = 0; i < 8; i++) nxt[i] = *(const float4*)(p + (size_t)i * HWPIX);
        }

        // Phase A: partial scores for this thread's 4 pixels over its 8 channels
        float4 ps = make_float4(0.f, 0.f, 0.f, 0.f);
        #pragma unroll
        for (int i = 0; i < 8; i++) {
            ps.x += qkr[i] * cur[i].x;
            ps.y += qkr[i] * cur[i].y;
            ps.z += qkr[i] * cur[i].z;
            ps.w += qkr[i] * cur[i].w;
        }
        red_s[4 * pq + 0][cg] = ps.x;
        red_s[4 * pq + 1][cg] = ps.y;
        red_s[4 * pq + 2][cg] = ps.z;
        red_s[4 * pq + 3][cg] = ps.w;
        __syncthreads();   // sync B: partials visible

        // distributed reduce: 8 threads per pixel, all 16 warps participate
        {
            const int p = tid >> 3, h = tid & 7;
            float s = red_s[p][4 * h] + red_s[p][4 * h + 1]
                    + red_s[p][4 * h + 2] + red_s[p][4 * h + 3];
            s += __shfl_down_sync(0xffffffffu, s, 4, 8);
            s += __shfl_down_sync(0xffffffffu, s, 2, 8);
            s += __shfl_down_sync(0xffffffffu, s, 1, 8);
            if (h == 0) {
                float nm = fmaxf(rmax_r, s);
                float cr = __expf(rmax_r - nm);
                float w  = __expf(s - nm);
                rsum_r = rsum_r * cr + w;
                rmax_r = nm;
                w_s[p]    = w;
                corr_s[p] = cr;
            }
        }
        __syncthreads();   // sync C: w/corr ready (also gates red_s reuse next iter)

        // Phase B: y = y*corr + w*x (registers only)
        {
            float4 wv = *(const float4*)&w_s[4 * pq];
            float4 cv = *(const float4*)&corr_s[4 * pq];
            #pragma unroll
            for (int i = 0; i < 8; i++) {
                yacc[i].x = yacc[i].x * cv.x + wv.x * cur[i].x;
                yacc[i].y = yacc[i].y * cv.y + wv.y * cur[i].y;
                yacc[i].z = yacc[i].z * cv.z + wv.z * cur[i].z;
                yacc[i].w = yacc[i].w * cv.w + wv.w * cur[i].w;
            }
        }
        #pragma unroll
        for (int i = 0; i < 8; i++) cur[i] = nxt[i];
    }

    // publish rsum, then normalize y -> tf32 bits into ysh[k][n] (pitch YPITCH)
    if ((tid & 7) == 0) rsum_s[tid >> 3] = rsum_r;
    __syncthreads();
    {
        float4 rs = *(const float4*)&rsum_s[4 * pq];
        float4 inv = make_float4(1.f / rs.x, 1.f / rs.y, 1.f / rs.z, 1.f / rs.w);
        #pragma unroll
        for (int i = 0; i < 8; i++) {
            int c = cg * 8 + i;
            float4 tv = make_float4(
                __uint_as_float(f2tf32(yacc[i].x * inv.x)),
                __uint_as_float(f2tf32(yacc[i].y * inv.y)),
                __uint_as_float(f2tf32(yacc[i].z * inv.z)),
                __uint_as_float(f2tf32(yacc[i].w * inv.w)));
            *(float4*)&ysh[c * YPITCH + 4 * pq] = tv;
        }
    }
    __syncthreads();

    // Epilogue GEMM on tensor cores (tf32 mma.sync m16n8k8):
    // out[o, p] = sum_c Wv[o,c] * y[c,p] + bv[o]
    // Warp w owns out-rows 16w..16w+15 x all 64 px; 8 n-tiles x 32 k-steps.
    {
        const int w  = tid >> 5;        // 0..15
        const int L  = tid & 31;
        const int r0 = 16 * w + (L >> 2);
        const int r1 = r0 + 8;
        const int cA = L & 3;           // A col offset / B row offset
        const int nB = L >> 2;          // B col offset within n-tile

        float acc[8][4];
        {
            float b0v = bv[r0], b1v = bv[r1];
            #pragma unroll
            for (int t = 0; t < 8; t++) {
                acc[t][0] = b0v; acc[t][1] = b0v;
                acc[t][2] = b1v; acc[t][3] = b1v;
            }
        }

        const float* wvA0 = g_wvt + (size_t)r0 * CH + cA;
        const float* wvA1 = g_wvt + (size_t)r1 * CH + cA;

        // 4-deep A-fragment prefetch to hide L2 latency
        unsigned abuf[4][4];
        #pragma unroll
        for (int s = 0; s < 3; s++) {
            int k0 = s * 8;
            abuf[s][0] = __float_as_uint(wvA0[k0]);
            abuf[s][1] = __float_as_uint(wvA1[k0]);
            abuf[s][2] = __float_as_uint(wvA0[k0 + 4]);
            abuf[s][3] = __float_as_uint(wvA1[k0 + 4]);
        }

        #pragma unroll 4
        for (int i = 0; i < 32; i++) {
            if (i + 3 < 32) {
                int k0 = (i + 3) * 8;
                int s  = (i + 3) & 3;
                abuf[s][0] = __float_as_uint(wvA0[k0]);
                abuf[s][1] = __float_as_uint(wvA1[k0]);
                abuf[s][2] = __float_as_uint(wvA0[k0 + 4]);
                abuf[s][3] = __float_as_uint(wvA1[k0 + 4]);
            }
            const int s  = i & 3;
            const int kb = i * 8 + cA;
            #pragma unroll
            for (int t = 0; t < 8; t++) {
                unsigned b0 = __float_as_uint(ysh[(size_t)kb * YPITCH + 8 * t + nB]);
                unsigned b1 = __float_as_uint(ysh[(size_t)(kb + 4) * YPITCH + 8 * t + nB]);
                mma_tf32(acc[t][0], acc[t][1], acc[t][2], acc[t][3],
                         abuf[s][0], abuf[s][1], abuf[s][2], abuf[s][3], b0, b1);
            }
        }

        #pragma unroll
        for (int t = 0; t < 8; t++) {
            int px = pix0 + 8 * t + 2 * cA;
            float* d0 = out + ((size_t)b * CH + r0) * HWPIX + px;
            float* d1 = out + ((size_t)b * CH + r1) * HWPIX + px;
            *(float2*)d0 = make_float2(acc[t][0], acc[t][1]);
            *(float2*)d1 = make_float2(acc[t][2], acc[t][3]);
        }
    }
}

extern "C" void kernel_launch(void* const* d_in, const int* in_sizes, int n_in,
                              void* d_out, int out_size)
{
    const float* tr = (const float*)d_in[0];   // [B, T]
    const float* x  = (const float*)d_in[1];   // [B, M, C, H, W]
    const float* Wq = (const float*)d_in[2];   // [C, T]
    const float* bq = (const float*)d_in[3];   // [C]
    const float* Wk = (const float*)d_in[4];   // [C, C]
    // d_in[5] = bk: constant across the softmax axis -> cancels, unused
    const float* Wv = (const float*)d_in[6];   // [C, C]
    const float* bv = (const float*)d_in[7];   // [C]
    float* out = (float*)d_out;                // [B, C, H, W]

    (void)in_sizes; (void)n_in; (void)out_size;

    cudaFuncSetAttribute(main_kernel, cudaFuncAttributeMaxDynamicSharedMemorySize, YSMEM_BYTES);

    prepA_kernel<<<128, 256>>>(tr, Wq, bq, Wv);
    prepB_kernel<<<dim3(8, BATCH), 256>>>(Wk);
    main_kernel<<<BATCH * (HWPIX / PIX), NTHREADS, YSMEM_BYTES>>>(x, bv, out);
}